// round 3
// baseline (speedup 1.0000x reference)
#include <cuda_runtime.h>
#include <cstdint>

#define NPTS 4096
#define BATCH 16
#define MCTR 1024
#define KNBR 64
#define FDIM 64
#define H1D  64
#define H2D  64
#define OUTD 128
#define R2C  0.04f
#define CAND_CAP 1024

#define FPS_BLOCKS 16
#define FEAT_ROWS 128
#define FEAT_BLOCKS ((BATCH * NPTS) / FEAT_ROWS)   // 512

// ---------------- device scratch (no allocations allowed) ----------------
__device__ int   g_idx[BATCH * MCTR];
__device__ float g_feat[(size_t)BATCH * NPTS * H1D];   // x @ W1[0:64,:]  (16 MB)

// =========================================================================
// Merged kernel: blocks 0..15 -> FPS (one batch each); blocks 16.. -> feat
// 512 threads per block. FPS and feat overlap on the chip.
// =========================================================================
struct MSmem {
    union {
        struct {
            float px[NPTS], py[NPTS], pz[NPTS];          // 48 KB
            unsigned long long part[2][16];              // double-buffered partials
        } fps;
        struct {
            float xx[FEAT_ROWS][65];                     // padded: no bank conflicts
            float w[64][64];
        } feat;
    } u;
};

__global__ __launch_bounds__(512) void fpsfeat_kernel(
    const float* __restrict__ pos, float* __restrict__ pos_s_out,
    const float* __restrict__ x,   const float* __restrict__ W1)
{
    extern __shared__ unsigned char smraw[];
    MSmem& sm = *reinterpret_cast<MSmem*>(smraw);
    int tid = threadIdx.x;

    if (blockIdx.x < FPS_BLOCKS) {
        // ------------------------- FPS -------------------------
        auto& S = sm.u.fps;
        int b = blockIdx.x;
        const float* pb = pos + (size_t)b * NPTS * 3;

        float px[8], py[8], pz[8], dst[8];
#pragma unroll
        for (int u = 0; u < 8; u++) {
            int i = tid + u * 512;
            float X = pb[i * 3 + 0], Y = pb[i * 3 + 1], Z = pb[i * 3 + 2];
            S.px[i] = X; S.py[i] = Y; S.pz[i] = Z;
            px[u] = X; py[u] = Y; pz[u] = Z;
            dst[u] = 1e10f;
        }
        __syncthreads();

        int   last = 0;
        float lx = S.px[0], ly = S.py[0], lz = S.pz[0];

        for (int m = 0; m < MCTR; m++) {
            if (tid == 0) {
                g_idx[b * MCTR + m] = last;
                float* po = pos_s_out + ((size_t)(b * MCTR + m)) * 3;
                po[0] = lx; po[1] = ly; po[2] = lz;
            }
            float bv = -1.0f; int bi = 0;
#pragma unroll
            for (int u = 0; u < 8; u++) {
                float dx = px[u] - lx, dy = py[u] - ly, dz = pz[u] - lz;
                float d  = fmaf(dx, dx, fmaf(dy, dy, dz * dz));
                float nd = fminf(dst[u], d);
                dst[u] = nd;
                int gi = tid + u * 512;
                if (nd > bv) { bv = nd; bi = gi; }   // ascending gi -> first occurrence
            }
            // pack: high=d2 bits (nonneg float, order-preserving), low=~idx
            // max(key) => max d2, ties -> min idx
            unsigned long long key =
                ((unsigned long long)__float_as_uint(bv) << 32) |
                (unsigned)(~(unsigned)bi);
#pragma unroll
            for (int off = 16; off; off >>= 1) {
                unsigned long long ok = __shfl_down_sync(0xffffffffu, key, off);
                if (ok > key) key = ok;
            }
            if ((tid & 31) == 0) S.part[m & 1][tid >> 5] = key;
            __syncthreads();
            unsigned long long best = S.part[m & 1][0];
#pragma unroll
            for (int w = 1; w < 16; w++) {
                unsigned long long k2 = S.part[m & 1][w];
                if (k2 > best) best = k2;
            }
            last = (int)(~(unsigned)best);
            lx = S.px[last]; ly = S.py[last]; lz = S.pz[last];
        }
    } else {
        // ------------------------- feat: g = x @ W1[0:64,:] -------------------------
        auto& S = sm.u.feat;
        size_t rbase = (size_t)(blockIdx.x - FPS_BLOCKS) * FEAT_ROWS;

        for (int i = tid; i < 64 * 64; i += 512) S.w[i >> 6][i & 63] = W1[i];
        for (int i = tid; i < FEAT_ROWS * 64; i += 512)
            S.xx[i >> 6][i & 63] = x[rbase * 64 + i];
        __syncthreads();

        int r = tid >> 2, q = tid & 3;
        float acc[16];
#pragma unroll
        for (int c = 0; c < 16; c++) acc[c] = 0.f;
        for (int k = 0; k < 64; k++) {
            float xv = S.xx[r][k];
#pragma unroll
            for (int c4 = 0; c4 < 4; c4++) {
                float4 w = *reinterpret_cast<const float4*>(&S.w[k][q * 16 + c4 * 4]);
                acc[c4 * 4 + 0] = fmaf(xv, w.x, acc[c4 * 4 + 0]);
                acc[c4 * 4 + 1] = fmaf(xv, w.y, acc[c4 * 4 + 1]);
                acc[c4 * 4 + 2] = fmaf(xv, w.z, acc[c4 * 4 + 2]);
                acc[c4 * 4 + 3] = fmaf(xv, w.w, acc[c4 * 4 + 3]);
            }
        }
        float* go = g_feat + (rbase + r) * 64 + q * 16;
#pragma unroll
        for (int c4 = 0; c4 < 4; c4++)
            *reinterpret_cast<float4*>(go + c4 * 4) =
                make_float4(acc[c4 * 4 + 0], acc[c4 * 4 + 1],
                            acc[c4 * 4 + 2], acc[c4 * 4 + 3]);
    }
}

// =========================================================================
// Per-center kernel (256 threads): ball query top-K + MLP + max pool.
// All 64 neighbors in one pass; 2 blocks/SM -> 4 warps/SMSP on FMA.
// =========================================================================
struct CKSmem {
    union {
        unsigned long long cand[CAND_CAP];   // 8 KB (selection)
        float W2s[64 * 64];                  // 16 KB (MLP)
    } u;
    float W3s[64 * 128];      // 32 KB
    float h1s[64][68];        // padded rows
    float h2s[64][68];
    float red[16][128];
    float W1bs[3][64];
    float b1s[64], b2s[64], b3s[128];
    float rel[KNBR][3];
    int   nbr[KNBR];
    float ctr[3];
    int   cnt;
    int   nvalid;
};

__global__ __launch_bounds__(256) void center_kernel(
    const float* __restrict__ pos,
    const float* __restrict__ W1, const float* __restrict__ b1,
    const float* __restrict__ W2, const float* __restrict__ b2,
    const float* __restrict__ W3, const float* __restrict__ b3,
    float* __restrict__ out)
{
    extern __shared__ unsigned char smraw[];
    CKSmem& s = *reinterpret_cast<CKSmem*>(smraw);

    int tid = threadIdx.x;
    int blk = blockIdx.x;
    int b = blk >> 10;
    const float* pb = pos + (size_t)b * NPTS * 3;

    if (tid == 0) {
        int ci = g_idx[blk];
        s.ctr[0] = pb[ci * 3 + 0];
        s.ctr[1] = pb[ci * 3 + 1];
        s.ctr[2] = pb[ci * 3 + 2];
        s.cnt = 0;
    }
    __syncthreads();
    float cx = s.ctr[0], cy = s.ctr[1], cz = s.ctr[2];

    // ---- phase 1: candidates within R^2, key = d2_bits<<32 | idx ----
    for (int i = tid; i < NPTS; i += 256) {
        float dx = pb[i * 3 + 0] - cx;
        float dy = pb[i * 3 + 1] - cy;
        float dz = pb[i * 3 + 2] - cz;
        float d2 = fmaf(dx, dx, fmaf(dy, dy, dz * dz));
        if (d2 <= R2C) {
            int p = atomicAdd(&s.cnt, 1);
            if (p < CAND_CAP)
                s.u.cand[p] = ((unsigned long long)__float_as_uint(d2) << 32) | (unsigned)i;
        }
    }
    __syncthreads();
    int n  = min(s.cnt, CAND_CAP);
    int nv = min(n, KNBR);

    // ---- phase 2: bitonic sort -> K smallest (d2, idx) ----
    if (n > KNBR) {
        int P = 1; while (P < n) P <<= 1;
        for (int i = n + tid; i < P; i += 256) s.u.cand[i] = ~0ull;
        __syncthreads();
        for (int k = 2; k <= P; k <<= 1)
            for (int j = k >> 1; j; j >>= 1) {
                for (int i = tid; i < P; i += 256) {
                    int ixj = i ^ j;
                    if (ixj > i) {
                        unsigned long long a = s.u.cand[i], c = s.u.cand[ixj];
                        bool up = ((i & k) == 0);
                        if ((a > c) == up) { s.u.cand[i] = c; s.u.cand[ixj] = a; }
                    }
                }
                __syncthreads();
            }
    }

    // ---- extract neighbors + rel ----
    if (tid < KNBR) {
        if (tid < nv) {
            int j = (int)(s.u.cand[tid] & 0xffffffffu);
            s.nbr[tid]    = j;
            s.rel[tid][0] = pb[j * 3 + 0] - cx;
            s.rel[tid][1] = pb[j * 3 + 1] - cy;
            s.rel[tid][2] = pb[j * 3 + 2] - cz;
        } else {
            s.nbr[tid] = 0;
            s.rel[tid][0] = 0.f; s.rel[tid][1] = 0.f; s.rel[tid][2] = 0.f;
        }
    }
    if (tid == 0) s.nvalid = nv;
    __syncthreads();   // cand no longer needed; union becomes W2s

    // ---- load weights to smem ----
    for (int i = tid; i < 64 * 64; i += 256)  s.u.W2s[i] = W2[i];
    for (int i = tid; i < 64 * 128; i += 256) s.W3s[i]   = W3[i];
    for (int i = tid; i < 3 * 64; i += 256)   s.W1bs[i >> 6][i & 63] = W1[64 * 64 + i];
    if (tid < 64)       { s.b1s[tid] = b1[tid]; s.b2s[tid] = b2[tid]; }
    else if (tid < 192) s.b3s[tid - 64] = b3[tid - 64];
    __syncthreads();

    int nvalid = s.nvalid;

    // ---- h1: thread = (neighbor nl=tid/4, 16 channels) ----
    {
        int nl = tid >> 2, q = tid & 3;
        int j = s.nbr[nl];
        const float4* gr = reinterpret_cast<const float4*>(
            g_feat + ((size_t)(b * NPTS + j)) * 64 + q * 16);
        float rx = s.rel[nl][0], ry = s.rel[nl][1], rz = s.rel[nl][2];
#pragma unroll
        for (int c4 = 0; c4 < 4; c4++) {
            float4 g = gr[c4];
            float v[4] = {g.x, g.y, g.z, g.w};
            float o[4];
#pragma unroll
            for (int c = 0; c < 4; c++) {
                int ch = q * 16 + c4 * 4 + c;
                float t = v[c];
                t = fmaf(rx, s.W1bs[0][ch], t);
                t = fmaf(ry, s.W1bs[1][ch], t);
                t = fmaf(rz, s.W1bs[2][ch], t);
                t += s.b1s[ch];
                o[c] = fmaxf(t, 0.f);
            }
            *reinterpret_cast<float4*>(&s.h1s[nl][q * 16 + c4 * 4]) =
                make_float4(o[0], o[1], o[2], o[3]);
        }
    }
    __syncthreads();

    // ---- h2: thread = (8 channels coct, 2 neighbors) ----
    {
        int coct = tid & 7, npair = tid >> 3;       // npair 0..31
        int n0 = 2 * npair, n1 = n0 + 1;
        float acc0[8], acc1[8];
#pragma unroll
        for (int c = 0; c < 8; c++) { acc0[c] = 0.f; acc1[c] = 0.f; }
        for (int k = 0; k < 64; k += 4) {
            float4 h0 = *reinterpret_cast<const float4*>(&s.h1s[n0][k]);
            float4 h1 = *reinterpret_cast<const float4*>(&s.h1s[n1][k]);
            float ha[4] = {h0.x, h0.y, h0.z, h0.w};
            float hb[4] = {h1.x, h1.y, h1.z, h1.w};
#pragma unroll
            for (int kk = 0; kk < 4; kk++) {
                const float4 wlo = *reinterpret_cast<const float4*>(&s.u.W2s[(k + kk) * 64 + coct * 8]);
                const float4 whi = *reinterpret_cast<const float4*>(&s.u.W2s[(k + kk) * 64 + coct * 8 + 4]);
                float wv[8] = {wlo.x, wlo.y, wlo.z, wlo.w, whi.x, whi.y, whi.z, whi.w};
#pragma unroll
                for (int c = 0; c < 8; c++) {
                    acc0[c] = fmaf(ha[kk], wv[c], acc0[c]);
                    acc1[c] = fmaf(hb[kk], wv[c], acc1[c]);
                }
            }
        }
#pragma unroll
        for (int c = 0; c < 8; c++) {
            int ch = coct * 8 + c;
            s.h2s[n0][ch] = fmaxf(acc0[c] + s.b2s[ch], 0.f);
            s.h2s[n1][ch] = fmaxf(acc1[c] + s.b2s[ch], 0.f);
        }
    }
    __syncthreads();

    // ---- h3 + max: thread = (8 channels c16, 4 neighbors nq) ----
    float mx[8];
#pragma unroll
    for (int c = 0; c < 8; c++) mx[c] = -1e30f;
    {
        int c16 = tid & 15, nq = tid >> 4;          // nq 0..15
        int nb0 = 4 * nq;
        float acc[4][8];
#pragma unroll
        for (int sN = 0; sN < 4; sN++)
#pragma unroll
            for (int c = 0; c < 8; c++) acc[sN][c] = 0.f;

        for (int k = 0; k < 64; k += 4) {
            float hv[4][4];
#pragma unroll
            for (int sN = 0; sN < 4; sN++) {
                float4 h = *reinterpret_cast<const float4*>(&s.h2s[nb0 + sN][k]);
                hv[sN][0] = h.x; hv[sN][1] = h.y; hv[sN][2] = h.z; hv[sN][3] = h.w;
            }
#pragma unroll
            for (int kk = 0; kk < 4; kk++) {
                const float4 wlo = *reinterpret_cast<const float4*>(&s.W3s[(k + kk) * 128 + c16 * 8]);
                const float4 whi = *reinterpret_cast<const float4*>(&s.W3s[(k + kk) * 128 + c16 * 8 + 4]);
                float wv[8] = {wlo.x, wlo.y, wlo.z, wlo.w, whi.x, whi.y, whi.z, whi.w};
#pragma unroll
                for (int sN = 0; sN < 4; sN++)
#pragma unroll
                    for (int c = 0; c < 8; c++)
                        acc[sN][c] = fmaf(hv[sN][kk], wv[c], acc[sN][c]);
            }
        }
#pragma unroll
        for (int sN = 0; sN < 4; sN++) {
            if (nb0 + sN < nvalid) {
#pragma unroll
                for (int c = 0; c < 8; c++) mx[c] = fmaxf(mx[c], acc[sN][c]);
            }
        }
        // stage partials: 16 nq-rows x 128 channels
#pragma unroll
        for (int c = 0; c < 8; c++) s.red[nq][c16 * 8 + c] = mx[c];
    }
    __syncthreads();

    if (tid < 128) {
        float v = s.red[0][tid];
#pragma unroll
        for (int w = 1; w < 16; w++) v = fmaxf(v, s.red[w][tid]);
        out[(size_t)blk * OUTD + tid] = v + s.b3s[tid];
    }
}

// =========================================================================
extern "C" void kernel_launch(void* const* d_in, const int* in_sizes, int n_in,
                              void* d_out, int out_size)
{
    const float* x   = (const float*)d_in[0];
    const float* pos = (const float*)d_in[1];
    const float* W1  = (const float*)d_in[2];
    const float* b1  = (const float*)d_in[3];
    const float* W2  = (const float*)d_in[4];
    const float* b2  = (const float*)d_in[5];
    const float* W3  = (const float*)d_in[6];
    const float* b3  = (const float*)d_in[7];

    float* out       = (float*)d_out;                          // [B, M, OUT]
    float* pos_s_out = out + (size_t)BATCH * MCTR * OUTD;      // [B, M, 3]

    cudaFuncSetAttribute(fpsfeat_kernel,
                         cudaFuncAttributeMaxDynamicSharedMemorySize,
                         (int)sizeof(MSmem));
    cudaFuncSetAttribute(center_kernel,
                         cudaFuncAttributeMaxDynamicSharedMemorySize,
                         (int)sizeof(CKSmem));

    fpsfeat_kernel<<<FPS_BLOCKS + FEAT_BLOCKS, 512, sizeof(MSmem)>>>(
        pos, pos_s_out, x, W1);
    center_kernel<<<BATCH * MCTR, 256, sizeof(CKSmem)>>>(
        pos, W1, b1, W2, b2, W3, b3, out);
}

// round 4
// speedup vs baseline: 1.4408x; 1.4408x over previous
#include <cuda_runtime.h>
#include <cstdint>

#define NPTS 4096
#define BATCH 16
#define MCTR 1024
#define KNBR 64
#define FDIM 64
#define H1D  64
#define H2D  64
#define OUTD 128
#define R2C  0.04f
#define CAND_CAP 768

#define FPS_BLOCKS 16
#define FEAT_ROWS 64
#define FEAT_BLOCKS ((BATCH * NPTS) / FEAT_ROWS)   // 1024

typedef unsigned long long ull;

// ---------------- device scratch (no allocations allowed) ----------------
__device__ int   g_idx[BATCH * MCTR];
__device__ float g_feat[(size_t)BATCH * NPTS * H1D];   // x @ W1[0:64,:]  (16 MB)

// ---------------- f32x2 packed helpers (Blackwell FFMA2) ----------------
__device__ __forceinline__ ull fma2(ull a, ull b, ull c) {
    ull d;
    asm("fma.rn.f32x2 %0, %1, %2, %3;" : "=l"(d) : "l"(a), "l"(b), "l"(c));
    return d;
}
__device__ __forceinline__ ull pack2(float lo, float hi) {
    ull d;
    asm("mov.b64 %0, {%1, %2};" : "=l"(d) : "f"(lo), "f"(hi));
    return d;
}
__device__ __forceinline__ float2 unpack2(ull v) {
    float2 r;
    asm("mov.b64 {%0, %1}, %2;" : "=f"(r.x), "=f"(r.y) : "l"(v));
    return r;
}

// =========================================================================
// Merged kernel: blocks 0..15 -> FPS (one batch each, 256 thr, 16 pts/thr);
// blocks 16.. -> feat (64 rows each). FPS and feat overlap on the chip.
// =========================================================================
struct alignas(16) MSmem {
    union {
        struct {
            float px[NPTS], py[NPTS], pz[NPTS];          // 48 KB
            ull   part[2][8];                            // double-buffered partials
        } fps;
        struct {
            float xx[FEAT_ROWS][65];
            float w[64][64];
        } feat;
    } u;
};

__global__ __launch_bounds__(256) void fpsfeat_kernel(
    const float* __restrict__ pos, float* __restrict__ pos_s_out,
    const float* __restrict__ x,   const float* __restrict__ W1)
{
    extern __shared__ unsigned char smraw[];
    MSmem& sm = *reinterpret_cast<MSmem*>(smraw);
    int tid = threadIdx.x;

    if (blockIdx.x < FPS_BLOCKS) {
        // ------------------------- FPS -------------------------
        auto& S = sm.u.fps;
        int b = blockIdx.x;
        const float* pb = pos + (size_t)b * NPTS * 3;

        float px[16], py[16], pz[16], dst[16];
#pragma unroll
        for (int u = 0; u < 16; u++) {
            int i = tid + u * 256;
            float X = pb[i * 3 + 0], Y = pb[i * 3 + 1], Z = pb[i * 3 + 2];
            S.px[i] = X; S.py[i] = Y; S.pz[i] = Z;
            px[u] = X; py[u] = Y; pz[u] = Z;
            dst[u] = 1e10f;
        }
        __syncthreads();

        int   last = 0;
        float lx = S.px[0], ly = S.py[0], lz = S.pz[0];

        for (int m = 0; m < MCTR; m++) {
            if (tid == 0) {
                g_idx[b * MCTR + m] = last;
                float* po = pos_s_out + ((size_t)(b * MCTR + m)) * 3;
                po[0] = lx; po[1] = ly; po[2] = lz;
            }
            float bv = -1.0f; int bi = 0;
#pragma unroll
            for (int u = 0; u < 16; u++) {
                float dx = px[u] - lx, dy = py[u] - ly, dz = pz[u] - lz;
                float d  = fmaf(dx, dx, fmaf(dy, dy, dz * dz));
                float nd = fminf(dst[u], d);
                dst[u] = nd;
                int gi = tid + u * 256;
                if (nd > bv) { bv = nd; bi = gi; }   // ascending gi -> first occurrence
            }
            // key: high = d2 bits (nonneg float, order-preserving), low = ~idx
            ull key = ((ull)__float_as_uint(bv) << 32) | (unsigned)(~(unsigned)bi);
#pragma unroll
            for (int off = 16; off; off >>= 1) {
                ull ok = __shfl_down_sync(0xffffffffu, key, off);
                if (ok > key) key = ok;
            }
            if ((tid & 31) == 0) S.part[m & 1][tid >> 5] = key;
            __syncthreads();
            ull best = S.part[m & 1][0];
#pragma unroll
            for (int w = 1; w < 8; w++) {
                ull k2 = S.part[m & 1][w];
                if (k2 > best) best = k2;
            }
            last = (int)(~(unsigned)best);
            lx = S.px[last]; ly = S.py[last]; lz = S.pz[last];
        }
    } else {
        // ---------------- feat: g = x @ W1[0:64,:]  (f32x2) ----------------
        auto& S = sm.u.feat;
        size_t rbase = (size_t)(blockIdx.x - FPS_BLOCKS) * FEAT_ROWS;

        for (int i = tid; i < 64 * 64; i += 256) S.w[i >> 6][i & 63] = W1[i];
        for (int i = tid; i < FEAT_ROWS * 64; i += 256)
            S.xx[i >> 6][i & 63] = x[rbase * 64 + i];
        __syncthreads();

        int r = tid >> 2, q = tid & 3;       // 64 rows x 16 channels
        ull acc[8];
#pragma unroll
        for (int c = 0; c < 8; c++) acc[c] = 0ull;   // (0.f,0.f)
        for (int k = 0; k < 64; k++) {
            float xv = S.xx[r][k];
            ull xb = pack2(xv, xv);
            const ulonglong2* wp = reinterpret_cast<const ulonglong2*>(&S.w[k][q * 16]);
            ulonglong2 w0 = wp[0], w1 = wp[1], w2 = wp[2], w3 = wp[3];
            acc[0] = fma2(xb, w0.x, acc[0]); acc[1] = fma2(xb, w0.y, acc[1]);
            acc[2] = fma2(xb, w1.x, acc[2]); acc[3] = fma2(xb, w1.y, acc[3]);
            acc[4] = fma2(xb, w2.x, acc[4]); acc[5] = fma2(xb, w2.y, acc[5]);
            acc[6] = fma2(xb, w3.x, acc[6]); acc[7] = fma2(xb, w3.y, acc[7]);
        }
        float* go = g_feat + (rbase + r) * 64 + q * 16;
#pragma unroll
        for (int c = 0; c < 4; c++) {
            float2 a = unpack2(acc[c * 2]), bq = unpack2(acc[c * 2 + 1]);
            *reinterpret_cast<float4*>(go + c * 4) = make_float4(a.x, a.y, bq.x, bq.y);
        }
    }
}

// =========================================================================
// Per-center kernel (256 threads, 2 blocks/SM): rank-count ball-query
// selection + f32x2 MLP + max pool.
// =========================================================================
struct alignas(16) CKSmem {
    union {
        ull   keys[CAND_CAP];     // 6 KB (selection)
        float W2s[64 * 64];       // 16 KB (MLP)
    } u;
    float W3s[64 * 128];          // 32 KB
    float h1s[64][68];            // 17.4 KB (rows 16B-aligned: 68*4=272B)
    float h2s[64][68];
    float red[8][128];            // 4 KB
    float W1bs[3][64];
    float b1s[64], b2s[64], b3s[128];
    float rel[KNBR][3];
    int   nbr[KNBR];
    float ctr[3];
    int   cnt;
    int   nvalid;
};

__global__ __launch_bounds__(256, 2) void center_kernel(
    const float* __restrict__ pos,
    const float* __restrict__ W1, const float* __restrict__ b1,
    const float* __restrict__ W2, const float* __restrict__ b2,
    const float* __restrict__ W3, const float* __restrict__ b3,
    float* __restrict__ out)
{
    extern __shared__ unsigned char smraw[];
    CKSmem& s = *reinterpret_cast<CKSmem*>(smraw);

    int tid = threadIdx.x;
    int blk = blockIdx.x;
    int b = blk >> 10;
    const float* pb = pos + (size_t)b * NPTS * 3;

    if (tid == 0) {
        int ci = g_idx[blk];
        s.ctr[0] = pb[ci * 3 + 0];
        s.ctr[1] = pb[ci * 3 + 1];
        s.ctr[2] = pb[ci * 3 + 2];
        s.cnt = 0;
    }
    // defaults for unused neighbor slots (ordered before rank-writes by the
    // barrier after the scan phase)
    if (tid < KNBR) {
        s.nbr[tid] = 0;
        s.rel[tid][0] = 0.f; s.rel[tid][1] = 0.f; s.rel[tid][2] = 0.f;
    }
    __syncthreads();
    float cx = s.ctr[0], cy = s.ctr[1], cz = s.ctr[2];

    // ---- phase 1: candidates within R^2, key = d2_bits<<32 | idx ----
    for (int i = tid; i < NPTS; i += 256) {
        float dx = pb[i * 3 + 0] - cx;
        float dy = pb[i * 3 + 1] - cy;
        float dz = pb[i * 3 + 2] - cz;
        float d2 = fmaf(dx, dx, fmaf(dy, dy, dz * dz));
        if (d2 <= R2C) {
            int p = atomicAdd(&s.cnt, 1);
            if (p < CAND_CAP)
                s.u.keys[p] = ((ull)__float_as_uint(d2) << 32) | (unsigned)i;
        }
    }
    __syncthreads();
    int n  = min(s.cnt, CAND_CAP);
    int nv = min(n, KNBR);

    // ---- phase 2: rank-count selection (exact top-K set by (d2, idx)) ----
    {
        ull myk[3]; int rnk[3];
#pragma unroll
        for (int t = 0; t < 3; t++) {
            int i = tid + t * 256;
            myk[t] = (i < n) ? s.u.keys[i] : ~0ull;
            rnk[t] = 0;
        }
        for (int j = 0; j < n; j++) {
            ull kj = s.u.keys[j];                 // broadcast
#pragma unroll
            for (int t = 0; t < 3; t++) rnk[t] += (kj < myk[t]) ? 1 : 0;
        }
#pragma unroll
        for (int t = 0; t < 3; t++) {
            int i = tid + t * 256;
            if (i < n && rnk[t] < KNBR) {
                int idx = (int)(myk[t] & 0xffffffffu);
                s.nbr[rnk[t]] = idx;
                s.rel[rnk[t]][0] = pb[idx * 3 + 0] - cx;
                s.rel[rnk[t]][1] = pb[idx * 3 + 1] - cy;
                s.rel[rnk[t]][2] = pb[idx * 3 + 2] - cz;
            }
        }
        if (tid == 0) s.nvalid = nv;
    }
    __syncthreads();   // keys dead; union becomes W2s

    // ---- load weights to smem ----
    for (int i = tid; i < 64 * 64; i += 256)  s.u.W2s[i] = W2[i];
    for (int i = tid; i < 64 * 128; i += 256) s.W3s[i]   = W3[i];
    for (int i = tid; i < 3 * 64; i += 256)   s.W1bs[i >> 6][i & 63] = W1[64 * 64 + i];
    if (tid < 64)       { s.b1s[tid] = b1[tid]; s.b2s[tid] = b2[tid]; }
    else if (tid < 192) s.b3s[tid - 64] = b3[tid - 64];
    __syncthreads();

    int nvalid = s.nvalid;

    // ---- h1: thread = (neighbor nl=tid/4, 16 channels) ----
    {
        int nl = tid >> 2, q = tid & 3;
        int j = s.nbr[nl];
        const float4* gr = reinterpret_cast<const float4*>(
            g_feat + ((size_t)(b * NPTS + j)) * 64 + q * 16);
        float rx = s.rel[nl][0], ry = s.rel[nl][1], rz = s.rel[nl][2];
#pragma unroll
        for (int c4 = 0; c4 < 4; c4++) {
            float4 g = gr[c4];
            float v[4] = {g.x, g.y, g.z, g.w};
            float o[4];
#pragma unroll
            for (int c = 0; c < 4; c++) {
                int ch = q * 16 + c4 * 4 + c;
                float t = v[c];
                t = fmaf(rx, s.W1bs[0][ch], t);
                t = fmaf(ry, s.W1bs[1][ch], t);
                t = fmaf(rz, s.W1bs[2][ch], t);
                t += s.b1s[ch];
                o[c] = fmaxf(t, 0.f);
            }
            *reinterpret_cast<float4*>(&s.h1s[nl][q * 16 + c4 * 4]) =
                make_float4(o[0], o[1], o[2], o[3]);
        }
    }
    __syncthreads();

    // ---- h2: thread = (c4g = 4 channels, ng = 4 neighbors), f32x2 ----
    {
        int c4g = tid & 15, ng = tid >> 4;
        int n0 = ng * 4;
        ull acc[4][2];
#pragma unroll
        for (int j = 0; j < 4; j++) { acc[j][0] = 0ull; acc[j][1] = 0ull; }
        for (int k = 0; k < 64; k++) {
            ulonglong2 w = *reinterpret_cast<const ulonglong2*>(&s.u.W2s[k * 64 + c4g * 4]);
#pragma unroll
            for (int j = 0; j < 4; j++) {
                float hv = s.h1s[n0 + j][k];
                ull hb = pack2(hv, hv);
                acc[j][0] = fma2(hb, w.x, acc[j][0]);
                acc[j][1] = fma2(hb, w.y, acc[j][1]);
            }
        }
        int ch = c4g * 4;
        float bb0 = s.b2s[ch], bb1 = s.b2s[ch + 1], bb2 = s.b2s[ch + 2], bb3 = s.b2s[ch + 3];
#pragma unroll
        for (int j = 0; j < 4; j++) {
            float2 p0 = unpack2(acc[j][0]), p1 = unpack2(acc[j][1]);
            float4 o = make_float4(fmaxf(p0.x + bb0, 0.f), fmaxf(p0.y + bb1, 0.f),
                                   fmaxf(p1.x + bb2, 0.f), fmaxf(p1.y + bb3, 0.f));
            *reinterpret_cast<float4*>(&s.h2s[n0 + j][ch]) = o;
        }
    }
    __syncthreads();

    // ---- h3 + max: thread = (c4g = 4 channels of 128, ng = 8 neighbors) ----
    {
        int c4g = tid & 31, ng = tid >> 5;
        int n0 = ng * 8;
        ull acc[8][2];
#pragma unroll
        for (int j = 0; j < 8; j++) { acc[j][0] = 0ull; acc[j][1] = 0ull; }
        for (int k = 0; k < 64; k++) {
            ulonglong2 w = *reinterpret_cast<const ulonglong2*>(&s.W3s[k * 128 + c4g * 4]);
#pragma unroll
            for (int j = 0; j < 8; j++) {
                float hv = s.h2s[n0 + j][k];
                ull hb = pack2(hv, hv);
                acc[j][0] = fma2(hb, w.x, acc[j][0]);
                acc[j][1] = fma2(hb, w.y, acc[j][1]);
            }
        }
        float mx[4] = {-1e30f, -1e30f, -1e30f, -1e30f};
#pragma unroll
        for (int j = 0; j < 8; j++) {
            if (n0 + j < nvalid) {
                float2 p0 = unpack2(acc[j][0]), p1 = unpack2(acc[j][1]);
                mx[0] = fmaxf(mx[0], p0.x);
                mx[1] = fmaxf(mx[1], p0.y);
                mx[2] = fmaxf(mx[2], p1.x);
                mx[3] = fmaxf(mx[3], p1.y);
            }
        }
        *reinterpret_cast<float4*>(&s.red[ng][c4g * 4]) =
            make_float4(mx[0], mx[1], mx[2], mx[3]);
    }
    __syncthreads();

    if (tid < 128) {
        float v = s.red[0][tid];
#pragma unroll
        for (int w = 1; w < 8; w++) v = fmaxf(v, s.red[w][tid]);
        out[(size_t)blk * OUTD + tid] = v + s.b3s[tid];
    }
}

// =========================================================================
extern "C" void kernel_launch(void* const* d_in, const int* in_sizes, int n_in,
                              void* d_out, int out_size)
{
    const float* x   = (const float*)d_in[0];
    const float* pos = (const float*)d_in[1];
    const float* W1  = (const float*)d_in[2];
    const float* b1  = (const float*)d_in[3];
    const float* W2  = (const float*)d_in[4];
    const float* b2  = (const float*)d_in[5];
    const float* W3  = (const float*)d_in[6];
    const float* b3  = (const float*)d_in[7];

    float* out       = (float*)d_out;                          // [B, M, OUT]
    float* pos_s_out = out + (size_t)BATCH * MCTR * OUTD;      // [B, M, 3]

    cudaFuncSetAttribute(fpsfeat_kernel,
                         cudaFuncAttributeMaxDynamicSharedMemorySize,
                         (int)sizeof(MSmem));
    cudaFuncSetAttribute(center_kernel,
                         cudaFuncAttributeMaxDynamicSharedMemorySize,
                         (int)sizeof(CKSmem));

    fpsfeat_kernel<<<FPS_BLOCKS + FEAT_BLOCKS, 256, sizeof(MSmem)>>>(
        pos, pos_s_out, x, W1);
    center_kernel<<<BATCH * MCTR, 256, sizeof(CKSmem)>>>(
        pos, W1, b1, W2, b2, W3, b3, out);
}